// round 11
// baseline (speedup 1.0000x reference)
#include <cuda_runtime.h>
#include <cuda_bf16.h>
#include <cstdint>

// RBF kernel matrix, int8-IMMA certified filter + rare precise recompute.
//   x_hat = rn(32x)/32 (clamped), e = x - x_hat (includes clamp error).
//   |dot - dot_hat| <= ||x_hat||*||e_y|| + ||e_x||*||y||   (exact Cauchy-Schwarz)
//   sq_hat - 2*bound > 88  =>  true sq > 88  =>  expf(-sq) underflows => 0.0f
//   else exact fp32 recompute (rare).
// x,y: [8192,128] f32. out: [8192,8192] f32.

#define NM 8192
#define KD 128
#define CTA_M 128
#define CTA_N 128

__device__ float g_x2unused[1]; // (kept slot; stats packed in g_xst/g_yst)
__device__ float4 g_xst[NM];   // (x2, ||e||, ||x_hat||, ||x||)
__device__ float4 g_yst[NM];
__device__ int8_t g_xq[NM * KD];
__device__ int8_t g_yq[NM * KD];

// ---------------- helpers ----------------
__device__ __forceinline__ uint32_t smem_u32(const void* p) {
    uint32_t a;
    asm("{ .reg .u64 t; cvta.to.shared.u64 t, %1; cvt.u32.u64 %0, t; }"
        : "=r"(a) : "l"(p));
    return a;
}
__device__ __forceinline__ void ldsm_x4(uint32_t* r, uint32_t addr) {
    asm volatile("ldmatrix.sync.aligned.m8n8.x4.shared.b16 {%0,%1,%2,%3}, [%4];"
                 : "=r"(r[0]), "=r"(r[1]), "=r"(r[2]), "=r"(r[3]) : "r"(addr));
}
__device__ __forceinline__ void imma_s8(int* d, const uint32_t* a, const uint32_t* b) {
    asm volatile(
        "mma.sync.aligned.m16n8k32.row.col.s32.s8.s8.s32 "
        "{%0,%1,%2,%3}, {%4,%5,%6,%7}, {%8,%9}, {%0,%1,%2,%3};"
        : "+r"(d[0]), "+r"(d[1]), "+r"(d[2]), "+r"(d[3])
        : "r"(a[0]), "r"(a[1]), "r"(a[2]), "r"(a[3]), "r"(b[0]), "r"(b[1]));
}
__device__ __forceinline__ void cp16(uint32_t dst, const void* src) {
    asm volatile("cp.async.cg.shared.global [%0], [%1], 16;" :: "r"(dst), "l"(src));
}

// exact value for non-certified elements (rare): fp32 dot from global
__device__ __noinline__ float precise_val(const float* __restrict__ X,
                                          const float* __restrict__ Y,
                                          int m, int n, float xpy) {
    const float4* xr = reinterpret_cast<const float4*>(X + (size_t)m * KD);
    const float4* yr = reinterpret_cast<const float4*>(Y + (size_t)n * KD);
    float dot = 0.0f;
#pragma unroll
    for (int i = 0; i < KD / 4; i++) {
        float4 a = xr[i], b = yr[i];
        dot = fmaf(a.x, b.x, dot); dot = fmaf(a.y, b.y, dot);
        dot = fmaf(a.z, b.z, dot); dot = fmaf(a.w, b.w, dot);
    }
    return __expf(-fmaxf(fmaf(-2.0f, dot, xpy), 0.0f));
}

// sq_hat from int dot; certify-zero test; else precise
__device__ __forceinline__ float filtered_val(const float* X, const float* Y,
                                              int m, int n, int dint,
                                              float xpy, float errB) {
    // dot_hat = dint / 1024 ; sq_hat = xpy - 2*dot_hat = xpy - dint/512
    float sqh = fmaf((float)dint, -0.001953125f, xpy);
    if (sqh > 88.0f + errB) return 0.0f;
    return precise_val(X, Y, m, n, xpy);
}

__device__ __forceinline__ int q8(float v) {
    int q = __float2int_rn(v * 32.0f);
    return max(-127, min(127, q));
}

// ---------------- prep: quantize + stats (warp per row) ----------------
__global__ void rbf_prep_kernel(const float* __restrict__ x,
                                const float* __restrict__ y) {
    int gw = (blockIdx.x * blockDim.x + threadIdx.x) >> 5;
    int lane = threadIdx.x & 31;
    if (gw >= 2 * NM) return;
    bool isX = gw < NM;
    int row = isX ? gw : gw - NM;
    const float* src = isX ? x : y;
    int8_t* qd = isX ? g_xq : g_yq;
    float4* st = isX ? g_xst : g_yst;

    float4 v = reinterpret_cast<const float4*>(src + (size_t)row * KD)[lane];
    int q0 = q8(v.x), q1 = q8(v.y), q2 = q8(v.z), q3 = q8(v.w);
    uint32_t packed = (uint32_t)(q0 & 0xFF) | ((uint32_t)(q1 & 0xFF) << 8)
                    | ((uint32_t)(q2 & 0xFF) << 16) | ((uint32_t)(q3 & 0xFF) << 24);
    reinterpret_cast<uint32_t*>(qd + (size_t)row * KD)[lane] = packed;

    const float inv = 0.03125f;  // 1/32
    float h0 = q0 * inv, h1 = q1 * inv, h2 = q2 * inv, h3 = q3 * inv;
    float e0 = v.x - h0, e1 = v.y - h1, e2 = v.z - h2, e3 = v.w - h3;

    float s2  = fmaf(v.x, v.x, fmaf(v.y, v.y, fmaf(v.z, v.z, v.w * v.w)));
    float eq2 = fmaf(e0, e0, fmaf(e1, e1, fmaf(e2, e2, e3 * e3)));
    float nq2 = fmaf(h0, h0, fmaf(h1, h1, fmaf(h2, h2, h3 * h3)));
#pragma unroll
    for (int o = 16; o > 0; o >>= 1) {
        s2  += __shfl_xor_sync(0xFFFFFFFFu, s2, o);
        eq2 += __shfl_xor_sync(0xFFFFFFFFu, eq2, o);
        nq2 += __shfl_xor_sync(0xFFFFFFFFu, nq2, o);
    }
    if (lane == 0)
        st[row] = make_float4(s2, sqrtf(eq2), sqrtf(nq2), sqrtf(s2));
}

// ---------------- main IMMA filter kernel ----------------
// CTA 128x128, 8 warps (2 M x 4 N), warp tile 64x32, full K=128 resident.
// smem 32 KB (2 CTA/SM): Aq [0,16K) 128 rows x 128B s8 (8 x 16B chunks,
// chunk ^= row&7); Bq [16K,32K) same.
// Epilogue identical in structure to the best (R6) kernel: direct float2
// stores of filtered values.
__global__ __launch_bounds__(256, 2)
void rbf_mma_kernel(const float* __restrict__ X,
                    const float* __restrict__ Y,
                    float* __restrict__ O) {
    extern __shared__ char sm[];
    __shared__ float4 x4s[CTA_M];
    __shared__ float4 y4s[CTA_N];

    const int tid = threadIdx.x;
    const int wid = tid >> 5;
    const int lane = tid & 31;
    const int wm = wid >> 2;       // 0..1 (64 rows)
    const int wn = wid & 3;        // 0..3 (32 cols)
    const int mBase = blockIdx.y * CTA_M;
    const int nBase = blockIdx.x * CTA_N;

    const uint32_t sA = smem_u32(sm);
    const uint32_t sB = sA + 16384u;

    // -------- fill: 1024 16B chunks per tensor (4 iters x 256 thr) --------
#pragma unroll
    for (int i = 0; i < 4; i++) {
        int idx = tid + i * 256;
        int r = idx >> 3, j = idx & 7;
        uint32_t off = (uint32_t)(r * 128 + ((j ^ (r & 7)) << 4));
        cp16(sA + off, g_xq + (size_t)(mBase + r) * KD + j * 16);
        cp16(sB + off, g_yq + (size_t)(nBase + r) * KD + j * 16);
    }
    asm volatile("cp.async.commit_group;" ::: "memory");

    if (tid < CTA_M) x4s[tid] = g_xst[mBase + tid];
    else             y4s[tid - CTA_M] = g_yst[nBase + (tid - CTA_M)];

    int acc[4][4][4];
#pragma unroll
    for (int mt = 0; mt < 4; mt++)
#pragma unroll
        for (int nt = 0; nt < 4; nt++)
#pragma unroll
            for (int r = 0; r < 4; r++) acc[mt][nt][r] = 0;

    // ldmatrix lane mappings (s8 m16n8k32 fragments)
    // A tile order: [m0-7,k0-15][m8-15,k0-15][m0-7,k16-31][m8-15,k16-31]
    const int a_row = wm * 64 + (lane & 7) + (((lane >> 3) & 1) << 3);
    const int a_kh  = lane >> 4;                 // chunk half (k16 sel)
    // B tile order (per ldsm covers 2 n-tiles): [n0-7,k0][n0-7,k16][n8-15,k0][n8-15,k16]
    const int b_row = wn * 32 + (lane & 7) + ((lane >> 4) << 3);
    const int b_kh  = (lane >> 3) & 1;

    asm volatile("cp.async.wait_group 0;" ::: "memory");
    __syncthreads();

    // -------- mainloop: 4 k32-steps --------
#pragma unroll
    for (int ks = 0; ks < 4; ks++) {
        const int kc = ks * 2;
        uint32_t bfr[2][4];
#pragma unroll
        for (int p = 0; p < 2; p++) {   // n-tile pairs: (0,1) and (2,3)
            int rr = b_row + p * 16;
            ldsm_x4(bfr[p], sB + (uint32_t)(rr * 128)
                          + (uint32_t)(((kc + b_kh) ^ (rr & 7)) << 4));
        }
#pragma unroll
        for (int mt = 0; mt < 4; mt++) {
            int rr = a_row + mt * 16;
            uint32_t afr[4];
            ldsm_x4(afr, sA + (uint32_t)(rr * 128)
                       + (uint32_t)(((kc + a_kh) ^ (rr & 7)) << 4));
#pragma unroll
            for (int p = 0; p < 2; p++) {
                imma_s8(acc[mt][2 * p],     afr, bfr[p]);       // n-tile 2p
                imma_s8(acc[mt][2 * p + 1], afr, bfr[p] + 2);   // n-tile 2p+1
            }
        }
    }

    // -------- epilogue (R6 structure): filtered values, direct float2 stores ----
    const int g  = lane >> 2;
    const int t4 = lane & 3;
#pragma unroll
    for (int mt = 0; mt < 4; mt++) {
        int mrow = wm * 64 + mt * 16 + g;
        float4 xa = x4s[mrow];
        float4 xb = x4s[mrow + 8];
        int m0 = mBase + mrow;
        float* orow0 = O + (size_t)m0 * NM + nBase;
        float* orow1 = orow0 + (size_t)8 * NM;
#pragma unroll
        for (int nt = 0; nt < 4; nt++) {
            int nc = wn * 32 + nt * 8 + t4 * 2;
            float4 ya = y4s[nc];
            float4 yb = y4s[nc + 1];
            const int* a4 = acc[mt][nt];
            int n0 = nBase + nc;
            // errB = 2*(||x_hat||*||e_y|| + ||e_x||*||y||) + margin
            float eAA = fmaf(2.0f, fmaf(xa.z, ya.y, xa.y * ya.w), 0.25f);
            float eAB = fmaf(2.0f, fmaf(xa.z, yb.y, xa.y * yb.w), 0.25f);
            float eBA = fmaf(2.0f, fmaf(xb.z, ya.y, xb.y * ya.w), 0.25f);
            float eBB = fmaf(2.0f, fmaf(xb.z, yb.y, xb.y * yb.w), 0.25f);
            float2 o0, o1;
            o0.x = filtered_val(X, Y, m0,     n0,     a4[0], xa.x + ya.x, eAA);
            o0.y = filtered_val(X, Y, m0,     n0 + 1, a4[1], xa.x + yb.x, eAB);
            o1.x = filtered_val(X, Y, m0 + 8, n0,     a4[2], xb.x + ya.x, eBA);
            o1.y = filtered_val(X, Y, m0 + 8, n0 + 1, a4[3], xb.x + yb.x, eBB);
            *reinterpret_cast<float2*>(orow0 + nc) = o0;
            *reinterpret_cast<float2*>(orow1 + nc) = o1;
        }
    }
}

// ---------------------------------------------------------------------------
extern "C" void kernel_launch(void* const* d_in, const int* in_sizes, int n_in,
                              void* d_out, int out_size) {
    const float* x = (const float*)d_in[0];
    const float* y = (const float*)d_in[1];
    float* out = (float*)d_out;

    cudaFuncSetAttribute(rbf_mma_kernel,
                         cudaFuncAttributeMaxDynamicSharedMemorySize, 32768);

    rbf_prep_kernel<<<2048, 256>>>(x, y);

    dim3 grid(NM / CTA_N, NM / CTA_M);   // (64, 64)
    rbf_mma_kernel<<<grid, 256, 32768>>>(x, y, out);
}

// round 12
// speedup vs baseline: 1.5983x; 1.5983x over previous
#include <cuda_runtime.h>
#include <cuda_bf16.h>
#include <cstdint>

// RBF kernel matrix, bf16-hi HMMA filter + rare precise recompute. (R6 structure)
//   Bound: |sq_hi - sq| <= 0.008*(||x||^2+||y||^2)  (bf16 rn eps=2^-8, AM-GM, margin)
//   sq_hi >= 89.2 + 0.008*(x2+y2)  =>  sq > 88  =>  expf(-sq) underflows => 0.0f
//   else: exact fp32 recompute (rare).
// R12 deltas vs R6: streaming (.cs) output stores, 8x8 supertile grid swizzle.
// x,y: [8192,128] f32. out: [8192,8192] f32.

#define NM 8192
#define KD 128
#define CTA_M 128
#define CTA_N 128
#define GRID_W (NM / CTA_N)   // 64 tiles per side
#define SUPER 8               // 8x8 CTA supertiles

__device__ float g_x2[NM];
__device__ float g_y2[NM];
__device__ __nv_bfloat16 g_xhi[NM * KD];
__device__ __nv_bfloat16 g_yhi[NM * KD];

// ---------------- helpers ----------------
__device__ __forceinline__ uint32_t smem_u32(const void* p) {
    uint32_t a;
    asm("{ .reg .u64 t; cvta.to.shared.u64 t, %1; cvt.u32.u64 %0, t; }"
        : "=r"(a) : "l"(p));
    return a;
}
__device__ __forceinline__ void ldsm_x4(uint32_t* r, uint32_t addr) {
    asm volatile("ldmatrix.sync.aligned.m8n8.x4.shared.b16 {%0,%1,%2,%3}, [%4];"
                 : "=r"(r[0]), "=r"(r[1]), "=r"(r[2]), "=r"(r[3]) : "r"(addr));
}
__device__ __forceinline__ void mma_bf16(float* d, const uint32_t* a, const uint32_t* b) {
    asm volatile(
        "mma.sync.aligned.m16n8k16.row.col.f32.bf16.bf16.f32 "
        "{%0,%1,%2,%3}, {%4,%5,%6,%7}, {%8,%9}, {%0,%1,%2,%3};"
        : "+f"(d[0]), "+f"(d[1]), "+f"(d[2]), "+f"(d[3])
        : "r"(a[0]), "r"(a[1]), "r"(a[2]), "r"(a[3]), "r"(b[0]), "r"(b[1]));
}
__device__ __forceinline__ void cp16(uint32_t dst, const void* src) {
    asm volatile("cp.async.cg.shared.global [%0], [%1], 16;" :: "r"(dst), "l"(src));
}
__device__ __forceinline__ void stg64_cs(float* p, float2 v) {
    asm volatile("st.global.cs.v2.f32 [%0], {%1,%2};"
                 :: "l"(p), "f"(v.x), "f"(v.y) : "memory");
}
__device__ __forceinline__ uint32_t bits(__nv_bfloat162 v) {
    return *reinterpret_cast<uint32_t*>(&v);
}

// exact value for non-underflow elements (rare): fp32 dot from global
__device__ __noinline__ float precise_val(const float* __restrict__ X,
                                          const float* __restrict__ Y,
                                          int m, int n, float xpy) {
    const float4* xr = reinterpret_cast<const float4*>(X + (size_t)m * KD);
    const float4* yr = reinterpret_cast<const float4*>(Y + (size_t)n * KD);
    float dot = 0.0f;
#pragma unroll
    for (int i = 0; i < KD / 4; i++) {
        float4 a = xr[i], b = yr[i];
        dot = fmaf(a.x, b.x, dot); dot = fmaf(a.y, b.y, dot);
        dot = fmaf(a.z, b.z, dot); dot = fmaf(a.w, b.w, dot);
    }
    return __expf(-fmaxf(fmaf(-2.0f, dot, xpy), 0.0f));
}

__device__ __forceinline__ float filtered_val(const float* X, const float* Y,
                                              int m, int n, float dot_hi, float xpy) {
    float sq_hi = fmaf(-2.0f, dot_hi, xpy);
    if (sq_hi < 89.2f + 0.008f * xpy)
        return precise_val(X, Y, m, n, xpy);
    return 0.0f;
}

// ---------------- prep: norms + bf16 hi (warp per row) ----------------
__global__ void rbf_prep_kernel(const float* __restrict__ x,
                                const float* __restrict__ y) {
    int gw = (blockIdx.x * blockDim.x + threadIdx.x) >> 5;
    int lane = threadIdx.x & 31;
    if (gw >= 2 * NM) return;
    bool isX = gw < NM;
    int row = isX ? gw : gw - NM;
    const float* src = isX ? x : y;
    __nv_bfloat16* hid = isX ? g_xhi : g_yhi;
    float* nrm = isX ? g_x2 : g_y2;

    float4 v = reinterpret_cast<const float4*>(src + (size_t)row * KD)[lane];
    __nv_bfloat162 h01 = __floats2bfloat162_rn(v.x, v.y);
    __nv_bfloat162 h23 = __floats2bfloat162_rn(v.z, v.w);
    *reinterpret_cast<uint2*>(hid + (size_t)row * KD + lane * 4) =
        make_uint2(bits(h01), bits(h23));

    float s = fmaf(v.x, v.x, fmaf(v.y, v.y, fmaf(v.z, v.z, v.w * v.w)));
#pragma unroll
    for (int o = 16; o > 0; o >>= 1) s += __shfl_xor_sync(0xFFFFFFFFu, s, o);
    if (lane == 0) nrm[row] = s;
}

// ---------------- main MMA filter kernel (R6 + .cs stores + swizzle) --------
// CTA 128x128, 8 warps (2 M x 4 N), warp tile 64x32, full K=128 resident.
// smem 64 KB (2 CTA/SM): Ahi [0,32K) = 2 k-panels x 16 KB (128 rows x 128B,
// 8 x 16B chunks, chunk ^= row&7); Bhi [32K,64K) same.
__global__ __launch_bounds__(256, 2)
void rbf_mma_kernel(const float* __restrict__ X,
                    const float* __restrict__ Y,
                    float* __restrict__ O) {
    extern __shared__ char sm[];
    __shared__ float x2s[CTA_M];
    __shared__ float y2s[CTA_N];

    const int tid = threadIdx.x;
    const int wid = tid >> 5;
    const int lane = tid & 31;
    const int wm = wid >> 2;       // 0..1 (64 rows)
    const int wn = wid & 3;        // 0..3 (32 cols)

    // 8x8 supertile swizzle: consecutive bid -> column-major within a
    // SUPER-wide band of tiles, so a resident wave shares A and B tiles.
    const int bid = blockIdx.x;
    const int band   = bid / (SUPER * GRID_W);     // 8-row band of tiles
    const int within = bid % (SUPER * GRID_W);
    const int tx = within / SUPER;                 // 0..63  (N tile)
    const int ty = band * SUPER + (within % SUPER);// M tile
    const int mBase = ty * CTA_M;
    const int nBase = tx * CTA_N;

    const uint32_t sA = smem_u32(sm);
    const uint32_t sB = sA + 32768u;

#pragma unroll
    for (int i = 0; i < 8; i++) {
        int idx = tid + i * 256;
        int r = idx >> 4, j = idx & 15;
        uint32_t off = (uint32_t)((j >> 3) * 16384 + r * 128 + (((j & 7) ^ (r & 7)) << 4));
        cp16(sA + off, g_xhi + (size_t)(mBase + r) * KD + j * 8);
        cp16(sB + off, g_yhi + (size_t)(nBase + r) * KD + j * 8);
    }
    asm volatile("cp.async.commit_group;" ::: "memory");

    if (tid < CTA_M) x2s[tid] = g_x2[mBase + tid];
    else             y2s[tid - CTA_M] = g_y2[nBase + (tid - CTA_M)];

    float acc[4][4][4];
#pragma unroll
    for (int mt = 0; mt < 4; mt++)
#pragma unroll
        for (int nt = 0; nt < 4; nt++)
#pragma unroll
            for (int r = 0; r < 4; r++) acc[mt][nt][r] = 0.0f;

    const int a_row = wm * 64 + (lane & 15);
    const int a_cs  = lane >> 4;
    const int b_row = wn * 32 + (lane & 7) + ((lane >> 4) << 3);
    const int b_cs  = (lane >> 3) & 1;

    asm volatile("cp.async.wait_group 0;" ::: "memory");
    __syncthreads();

    // -------- mainloop: 8 k16-steps, 16 MMA each --------
#pragma unroll
    for (int ks = 0; ks < 8; ks++) {
        const uint32_t pnl = (uint32_t)((ks >> 2) * 16384);
        const int kc = (ks & 3) * 2;
        uint32_t bh[2][4];
#pragma unroll
        for (int pr = 0; pr < 2; pr++) {
            int rr = b_row + pr * 16;
            ldsm_x4(bh[pr], sB + pnl + (uint32_t)(rr * 128)
                          + (uint32_t)(((kc + b_cs) ^ (rr & 7)) << 4));
        }
#pragma unroll
        for (int mt = 0; mt < 4; mt++) {
            int rr = a_row + mt * 16;
            uint32_t ah[4];
            ldsm_x4(ah, sA + pnl + (uint32_t)(rr * 128)
                      + (uint32_t)(((kc + a_cs) ^ (rr & 7)) << 4));
#pragma unroll
            for (int pr = 0; pr < 2; pr++) {
                mma_bf16(acc[mt][2 * pr],     ah, bh[pr]);
                mma_bf16(acc[mt][2 * pr + 1], ah, bh[pr] + 2);
            }
        }
    }

    // -------- epilogue: filtered values, streaming float2 stores --------
    const int g  = lane >> 2;
    const int t4 = lane & 3;
#pragma unroll
    for (int mt = 0; mt < 4; mt++) {
        int mrow = wm * 64 + mt * 16 + g;
        float xa = x2s[mrow];
        float xb = x2s[mrow + 8];
        int m0 = mBase + mrow;
        float* orow0 = O + (size_t)m0 * NM + nBase;
        float* orow1 = orow0 + (size_t)8 * NM;
#pragma unroll
        for (int nt = 0; nt < 4; nt++) {
            int nc = wn * 32 + nt * 8 + t4 * 2;
            float ya = y2s[nc];
            float yb = y2s[nc + 1];
            const float* a4 = acc[mt][nt];
            int n0 = nBase + nc;
            float2 o0, o1;
            o0.x = filtered_val(X, Y, m0,     n0,     a4[0], xa + ya);
            o0.y = filtered_val(X, Y, m0,     n0 + 1, a4[1], xa + yb);
            o1.x = filtered_val(X, Y, m0 + 8, n0,     a4[2], xb + ya);
            o1.y = filtered_val(X, Y, m0 + 8, n0 + 1, a4[3], xb + yb);
            stg64_cs(orow0 + nc, o0);
            stg64_cs(orow1 + nc, o1);
        }
    }
}

// ---------------------------------------------------------------------------
extern "C" void kernel_launch(void* const* d_in, const int* in_sizes, int n_in,
                              void* d_out, int out_size) {
    const float* x = (const float*)d_in[0];
    const float* y = (const float*)d_in[1];
    float* out = (float*)d_out;

    cudaFuncSetAttribute(rbf_mma_kernel,
                         cudaFuncAttributeMaxDynamicSharedMemorySize, 65536);

    rbf_prep_kernel<<<2048, 256>>>(x, y);

    rbf_mma_kernel<<<GRID_W * GRID_W, 256, 65536>>>(x, y, out);
}